// round 8
// baseline (speedup 1.0000x reference)
#include <cuda_runtime.h>
#include <cstddef>

// Fixed shapes
constexpr int B = 32;
constexpr int C = 256;
constexpr int H = 64;
constexpr int HW = H * H;           // 4096 pixels
constexpr int N = 2048;             // anchors per batch
constexpr int CHUNK = 4;            // channels per CTA
constexpr int NCHUNKS = C / CHUNK;  // 64
constexpr int THREADS = 512;        // 16 warps
constexpr size_t SMEM_BYTES = (size_t)HW * CHUNK * 4;  // 64 KB -> 3 CTAs/SM

__global__ __launch_bounds__(THREADS, 3)
void bilinear_gather_kernel(const float* __restrict__ fm,
                            const float* __restrict__ anchors,
                            float* __restrict__ out)
{
    extern __shared__ float s[];     // pixel-major: s[p*4 + ch], 4096 x float4

    const int blk   = blockIdx.x;
    const int b     = blk >> 6;      // / NCHUNKS
    const int chunk = blk & 63;      // % NCHUNKS

    // ---- Stage + transpose to pixel-major.
    // Thread owns pixel p: 4 scalar LDG (each perfectly coalesced across the
    // warp: stride-1 floats within one channel plane) -> one STS.128
    // (consecutive lanes -> conflict-free).
    {
        const float* __restrict__ src =
            fm + ((size_t)b * C + (size_t)chunk * CHUNK) * HW;
        float4* __restrict__ s4 = reinterpret_cast<float4*>(s);
        #pragma unroll
        for (int p = threadIdx.x; p < HW; p += THREADS) {
            float4 v;
            v.x = src[0 * HW + p];
            v.y = src[1 * HW + p];
            v.z = src[2 * HW + p];
            v.w = src[3 * HW + p];
            s4[p] = v;
        }
    }
    __syncthreads();

    const float2* __restrict__ anc2 =
        reinterpret_cast<const float2*>(anchors + (size_t)b * N * 2);
    float* __restrict__ outb = out + (size_t)b * N * C + (size_t)chunk * CHUNK;

    // ---- Quad gather: warp = 8 anchors x 4 channels.
    // lane = aid*4 + ch; the 4 lanes of a quad read 4 consecutive banks per
    // corner -> 8 random bank-groups/instr instead of 32 random banks.
    const int lane = threadIdx.x & 31;
    const int warp = threadIdx.x >> 5;
    const int aid  = lane >> 2;      // 0..7
    const int ch   = lane & 3;       // 0..3

    for (int n = warp * 8 + aid; n < N; n += (THREADS / 4)) {
        float2 a = anc2[n];          // 8 consecutive anchors/warp -> 64B, L1 hit
        float px = fminf(fmaxf(a.x * 63.0f, 0.0f), 63.0f);
        float py = fminf(fmaxf(a.y * 63.0f, 0.0f), 63.0f);

        float fx = floorf(px), fy = floorf(py);
        float cx = ceilf(px),  cy = ceilf(py);   // matches reference (rb==lt when integral)
        int xl = (int)fx, yl = (int)fy;
        int xr = (int)cx, yr = (int)cy;
        float dx = px - fx;
        float dy = py - fy;

        int i_lt = (yl * H + xl) * CHUNK + ch;
        int i_rt = (yl * H + xr) * CHUNK + ch;
        int i_lb = (yr * H + xl) * CHUNK + ch;
        int i_rb = (yr * H + xr) * CHUNK + ch;

        float vlt = s[i_lt];
        float vrt = s[i_rt];
        float vlb = s[i_lb];
        float vrb = s[i_rb];

        float vt = fmaf(vrt - vlt, dx, vlt);
        float vb = fmaf(vrb - vlb, dx, vlb);
        float r  = fmaf(vb - vt, dy, vt);

        // Quad writes 16 contiguous bytes (coalesced within the quad).
        outb[(size_t)n * C + ch] = r;
    }
}

extern "C" void kernel_launch(void* const* d_in, const int* in_sizes, int n_in,
                              void* d_out, int out_size)
{
    const float* fm      = (const float*)d_in[0];  // (32,256,64,64) fp32
    const float* anchors = (const float*)d_in[1];  // (32,2048,2) fp32
    float* out           = (float*)d_out;          // (32,2048,256) fp32

    cudaFuncSetAttribute(bilinear_gather_kernel,
                         cudaFuncAttributeMaxDynamicSharedMemorySize,
                         (int)SMEM_BYTES);

    dim3 grid(B * NCHUNKS);   // 2048 CTAs
    dim3 block(THREADS);
    bilinear_gather_kernel<<<grid, block, SMEM_BYTES>>>(fm, anchors, out);
}

// round 10
// speedup vs baseline: 1.0301x; 1.0301x over previous
#include <cuda_runtime.h>
#include <cstddef>

// Fixed shapes
constexpr int B = 32;
constexpr int C = 256;
constexpr int H = 64;
constexpr int HW = H * H;           // 4096 pixels
constexpr int N = 2048;             // anchors per batch
constexpr int CHUNK = 4;            // channels per CTA
constexpr int NCHUNKS = C / CHUNK;  // 64
constexpr int THREADS = 512;        // 16 warps
constexpr size_t SMEM_BYTES = (size_t)HW * CHUNK * 4;  // 64 KB -> 3 CTAs/SM

__device__ __forceinline__ float4 lerp4(float4 a, float4 b, float t) {
    return make_float4(fmaf(b.x - a.x, t, a.x),
                       fmaf(b.y - a.y, t, a.y),
                       fmaf(b.z - a.z, t, a.z),
                       fmaf(b.w - a.w, t, a.w));
}

__global__ __launch_bounds__(THREADS, 3)
void bilinear_gather_kernel(const float* __restrict__ fm,
                            const float* __restrict__ anchors,
                            float* __restrict__ out)
{
    extern __shared__ float4 s4[];   // pixel-major: s4[p] = {c0,c1,c2,c3}

    const int blk   = blockIdx.x;
    const int b     = blk >> 6;      // / NCHUNKS
    const int chunk = blk & 63;      // % NCHUNKS

    // ---- Stage + transpose to pixel-major.
    // Thread owns pixel p: 4 scalar LDG (each fully coalesced across the warp:
    // stride-1 floats within one channel plane) -> one STS.128 with consecutive
    // lane addresses (natively conflict-free, no swizzle needed).
    {
        const float* __restrict__ src =
            fm + ((size_t)b * C + (size_t)chunk * CHUNK) * HW;
        #pragma unroll
        for (int p = threadIdx.x; p < HW; p += THREADS) {
            float4 v;
            v.x = src[0 * HW + p];
            v.y = src[1 * HW + p];
            v.z = src[2 * HW + p];
            v.w = src[3 * HW + p];
            s4[p] = v;
        }
    }
    __syncthreads();

    const float2* __restrict__ anc2 =
        reinterpret_cast<const float2*>(anchors + (size_t)b * N * 2);
    float* __restrict__ outb = out + (size_t)b * N * C + (size_t)chunk * CHUNK;

    // ---- Gather: one thread per anchor (coordinate math computed ONCE per
    // anchor), 4x LDS.128 per anchor. Fixed 4-iteration loop, unrolled for
    // LDS-level ILP (up to 16 independent shared loads in flight).
    #pragma unroll
    for (int i = 0; i < N / THREADS; ++i) {
        const int n = i * THREADS + threadIdx.x;

        float2 a = anc2[n];
        float px = fminf(fmaxf(a.x * 63.0f, 0.0f), 63.0f);
        float py = fminf(fmaxf(a.y * 63.0f, 0.0f), 63.0f);

        float fx = floorf(px), fy = floorf(py);
        float cx = ceilf(px),  cy = ceilf(py);   // matches reference (rb==lt when integral)
        int xl = (int)fx, yl = (int)fy;
        int xr = (int)cx, yr = (int)cy;
        float dx = px - fx;
        float dy = py - fy;

        float4 vlt = s4[yl * H + xl];
        float4 vrt = s4[yl * H + xr];
        float4 vlb = s4[yr * H + xl];
        float4 vrb = s4[yr * H + xr];

        float4 vt = lerp4(vlt, vrt, dx);
        float4 vb = lerp4(vlb, vrb, dx);
        float4 r  = lerp4(vt, vb, dy);

        // 16 contiguous bytes per anchor (STG.128).
        *reinterpret_cast<float4*>(outb + (size_t)n * C) = r;
    }
}

extern "C" void kernel_launch(void* const* d_in, const int* in_sizes, int n_in,
                              void* d_out, int out_size)
{
    const float* fm      = (const float*)d_in[0];  // (32,256,64,64) fp32
    const float* anchors = (const float*)d_in[1];  // (32,2048,2) fp32
    float* out           = (float*)d_out;          // (32,2048,256) fp32

    cudaFuncSetAttribute(bilinear_gather_kernel,
                         cudaFuncAttributeMaxDynamicSharedMemorySize,
                         (int)SMEM_BYTES);

    dim3 grid(B * NCHUNKS);   // 2048 CTAs
    dim3 block(THREADS);
    bilinear_gather_kernel<<<grid, block, SMEM_BYTES>>>(fm, anchors, out);
}